// round 1
// baseline (speedup 1.0000x reference)
#include <cuda_runtime.h>
#include <cstdint>

// ---------------- device scratch (no allocations allowed) ----------------
__device__ __align__(16) float2 g_U[256];        // 16x16 variational unitary, row-major [i][j]
__device__ float  g_part[512 * 8];               // per-block partial sums: [blk][0..3]=sum, [4..7]=sumsq
__device__ __align__(16) float g_scale[8];       // [0..3]=scale_w, [4..7]=shift_w

// ---------------- K1: build U (runs once per launch, 16 threads) ----------
struct cd { double re, im; };
__device__ __forceinline__ cd cmul(cd a, cd b) { return {a.re*b.re - a.im*b.im, a.re*b.im + a.im*b.re}; }
__device__ __forceinline__ cd cadd(cd a, cd b) { return {a.re + b.re, a.im + b.im}; }

__global__ void k_build_U(const float* __restrict__ vp) {
    int j = threadIdx.x;            // column index 0..15
    if (j >= 16) return;
    cd st[16];
    #pragma unroll
    for (int i = 0; i < 16; i++) st[i] = { (i == j) ? 1.0 : 0.0, 0.0 };

    for (int l = 0; l < 3; l++) {
        for (int w = 0; w < 4; w++) {
            double tx = vp[(l*4 + w)*3 + 0];
            double ty = vp[(l*4 + w)*3 + 1];
            double tz = vp[(l*4 + w)*3 + 2];
            double cx, sx, cy, sy, cz, sz;
            sincos(tx*0.5, &sx, &cx);
            sincos(ty*0.5, &sy, &cy);
            sincos(tz*0.5, &sz, &cz);
            // M = RY * RX
            cd M00{ cy*cx,  sy*sx }, M01{ -sy*cx, -cy*sx };
            cd M10{ sy*cx, -cy*sx }, M11{  cy*cx, -sy*sx };
            // G = RZ * M  (RZ = diag(e^{-iz/2}, e^{+iz/2}))
            cd e0{ cz, -sz }, e1{ cz, sz };
            cd G00 = cmul(e0, M00), G01 = cmul(e0, M01);
            cd G10 = cmul(e1, M10), G11 = cmul(e1, M11);
            int mask = 8 >> w;      // wire w lives at bit (3-w)
            for (int i = 0; i < 16; i++) {
                if (i & mask) continue;
                cd s0 = st[i], s1 = st[i | mask];
                st[i]        = cadd(cmul(G00, s0), cmul(G01, s1));
                st[i | mask] = cadd(cmul(G10, s0), cmul(G11, s1));
            }
        }
        // CNOT chain: control w (bit 3-w), target w+1 (bit 2-w)
        for (int w = 0; w < 3; w++) {
            int cm = 8 >> w, tm = 4 >> w;
            cd tmp[16];
            for (int i = 0; i < 16; i++) tmp[i] = st[(i & cm) ? (i ^ tm) : i];
            for (int i = 0; i < 16; i++) st[i] = tmp[i];
        }
    }
    for (int i = 0; i < 16; i++)
        g_U[i*16 + j] = make_float2((float)st[i].re, (float)st[i].im);
}

// ---------------- K2: pool + features + circuit + raw out + partial stats --
// Block: 256 threads = 8 warps. Each warp processes 16 samples (8 pairs;
// lanes 0-15 handle sample A of the pair, lanes 16-31 sample B in the
// quantum phase). Block covers 128 samples.
__global__ __launch_bounds__(256) void k_main(
    const float* __restrict__ x, const float* __restrict__ W,
    const float* __restrict__ b, float* __restrict__ out)
{
    const int lane = threadIdx.x & 31;
    const int wid  = threadIdx.x >> 5;
    const int h    = lane >> 4;       // half within warp
    const int p    = lane & 15;       // basis-state / row index

    __shared__ float sPool[8][2][24][4];   // [warp][half][col][rowbin]
    __shared__ float sPart[16][8];         // per warp-half running sums

    // Preload this lane's U row into registers (fixed across all samples).
    float Ur[16], Ui[16];
    {
        const float4* row = reinterpret_cast<const float4*>(g_U + p*16);
        #pragma unroll
        for (int q = 0; q < 8; q++) {
            float4 u = row[q];
            Ur[q*2+0] = u.x; Ui[q*2+0] = u.y;
            Ur[q*2+1] = u.z; Ui[q*2+1] = u.w;
        }
    }
    const float4 wrow = reinterpret_cast<const float4*>(W)[p]; // W[p][0..3]
    const float4 bv   = *reinterpret_cast<const float4*>(b);

    float runS0=0, runS1=0, runS2=0, runS3=0;
    float runQ0=0, runQ1=0, runQ2=0, runQ3=0;

    const int sampleBase = blockIdx.x * 128 + wid * 16;

    for (int pp = 0; pp < 8; pp++) {
        // ---- pooling: lanes 0-23 = columns 0-23, two samples sequentially
        #pragma unroll
        for (int hh = 0; hh < 2; hh++) {
            int s = sampleBase + pp*2 + hh;
            if (lane < 24) {
                const float* basep = x + (size_t)s * 784 + lane;
                float a0=0, a1=0, a2=0, a3=0;
                #pragma unroll
                for (int r = 0; r < 24; r++) {
                    float v = __ldg(basep + r*28);
                    if      (r < 6)  a0 += v;
                    else if (r < 12) a1 += v;
                    else if (r < 18) a2 += v;
                    else             a3 += v;
                }
                *reinterpret_cast<float4*>(&sPool[wid][hh][lane][0]) =
                    make_float4(a0, a1, a2, a3);
            }
        }
        __syncwarp();

        // ---- pooled value for this lane's basis index p: p = rb*4 + cb
        const int cb = p & 3, rb = p >> 2;
        float v = 0.f;
        #pragma unroll
        for (int d = 0; d < 6; d++) v += sPool[wid][h][cb*6 + d][rb];
        v *= (1.0f / 36.0f);

        // ---- feats = pooled @ W + b   (butterfly over 16 lanes per half)
        float f0 = v*wrow.x, f1 = v*wrow.y, f2 = v*wrow.z, f3 = v*wrow.w;
        #pragma unroll
        for (int m = 1; m < 16; m <<= 1) {
            f0 += __shfl_xor_sync(0xffffffffu, f0, m);
            f1 += __shfl_xor_sync(0xffffffffu, f1, m);
            f2 += __shfl_xor_sync(0xffffffffu, f2, m);
            f3 += __shfl_xor_sync(0xffffffffu, f3, m);
        }
        f0 += bv.x; f1 += bv.y; f2 += bv.z; f3 += bv.w;

        // ---- encoded product state magnitudes
        float c0,s0,c1,s1,c2,s2,c3,s3;
        __sincosf(0.5f*f0, &s0, &c0);
        __sincosf(0.5f*f1, &s1, &c1);
        __sincosf(0.5f*f2, &s2, &c2);
        __sincosf(0.5f*f3, &s3, &c3);
        float w01[4] = { c0*c1, c0*s1, s0*c1, s0*s1 };  // wires 0,1 (bits 3,2)
        float w23[4] = { c2*c3, c2*s3, s2*c3, s2*s3 };  // wires 2,3 (bits 1,0)

        // ---- amp_p = sum_j U[p][j] * m_j * (-i)^popc(j)
        float ar = 0.f, ai = 0.f;
        #pragma unroll
        for (int j = 0; j < 16; j++) {
            float m = w01[j >> 2] * w23[j & 3];
            const int pm = __popc(j) & 3;   // compile-time per unrolled j
            if      (pm == 0) { ar += Ur[j]*m; ai += Ui[j]*m; }
            else if (pm == 1) { ar += Ui[j]*m; ai -= Ur[j]*m; }
            else if (pm == 2) { ar -= Ur[j]*m; ai -= Ui[j]*m; }
            else              { ar -= Ui[j]*m; ai += Ur[j]*m; }
        }
        float prob = ar*ar + ai*ai;

        // ---- expZ per wire: signed butterfly over 16 lanes per half
        float z[4];
        #pragma unroll
        for (int w = 0; w < 4; w++) {
            float vv = (p & (8 >> w)) ? -prob : prob;
            #pragma unroll
            for (int m = 1; m < 16; m <<= 1)
                vv += __shfl_xor_sync(0xffffffffu, vv, m);
            z[w] = vv;
        }

        if (p == 0) {
            int s = sampleBase + pp*2 + h;
            reinterpret_cast<float4*>(out)[s] = make_float4(z[0], z[1], z[2], z[3]);
            runS0 += z[0]; runS1 += z[1]; runS2 += z[2]; runS3 += z[3];
            runQ0 += z[0]*z[0]; runQ1 += z[1]*z[1];
            runQ2 += z[2]*z[2]; runQ3 += z[3]*z[3];
        }
        __syncwarp();
    }

    // ---- deterministic block reduction of stats (no atomics)
    if (p == 0) {
        int idx = wid*2 + h;
        sPart[idx][0] = runS0; sPart[idx][1] = runS1;
        sPart[idx][2] = runS2; sPart[idx][3] = runS3;
        sPart[idx][4] = runQ0; sPart[idx][5] = runQ1;
        sPart[idx][6] = runQ2; sPart[idx][7] = runQ3;
    }
    __syncthreads();
    if (threadIdx.x < 8) {
        float t = 0.f;
        #pragma unroll
        for (int k = 0; k < 16; k++) t += sPart[k][threadIdx.x];
        g_part[blockIdx.x * 8 + threadIdx.x] = t;
    }
}

// ---------------- K3a: reduce partials -> batchnorm scale/shift ------------
__global__ void k_reduce(const float* __restrict__ gamma,
                         const float* __restrict__ beta,
                         int nblk, float invB)
{
    __shared__ float red[32][8];
    __shared__ float tot[8];
    int t = threadIdx.x;              // 256 threads
    int w = t & 7, g = t >> 3;        // 32 groups x 8 values
    float s = 0.f;
    for (int q = g; q < nblk; q += 32) s += g_part[q*8 + w];
    red[g][w] = s;
    __syncthreads();
    if (t < 8) {
        float tt = 0.f;
        #pragma unroll
        for (int g2 = 0; g2 < 32; g2++) tt += red[g2][t];
        tot[t] = tt;
    }
    __syncthreads();
    if (t < 4) {
        float mu  = tot[t] * invB;
        float var = tot[4 + t] * invB - mu*mu;   // biased var (ddof=0)
        float sc  = gamma[t] * rsqrtf(var + 1e-5f);
        g_scale[t]     = sc;
        g_scale[4 + t] = beta[t] - mu * sc;
    }
}

// ---------------- K3b: normalize in place (vectorized) ---------------------
__global__ void k_norm(float* __restrict__ out, int B)
{
    int i = blockIdx.x * blockDim.x + threadIdx.x;
    if (i >= B) return;
    float4 sc = *reinterpret_cast<const float4*>(&g_scale[0]);
    float4 sh = *reinterpret_cast<const float4*>(&g_scale[4]);
    float4 r  = reinterpret_cast<float4*>(out)[i];
    r.x = r.x*sc.x + sh.x;
    r.y = r.y*sc.y + sh.y;
    r.z = r.z*sc.z + sh.z;
    r.w = r.w*sc.w + sh.w;
    reinterpret_cast<float4*>(out)[i] = r;
}

// ---------------- launch ----------------------------------------------------
extern "C" void kernel_launch(void* const* d_in, const int* in_sizes, int n_in,
                              void* d_out, int out_size)
{
    const float* x     = (const float*)d_in[0];  // [B,1,28,28]
    const float* W     = (const float*)d_in[1];  // [16,4]
    const float* b     = (const float*)d_in[2];  // [4]
    const float* vp    = (const float*)d_in[3];  // [3,4,3]
    const float* gamma = (const float*)d_in[4];  // [4]
    const float* beta  = (const float*)d_in[5];  // [4]
    float* out = (float*)d_out;                  // [B,4]

    int B = in_sizes[0] / 784;                   // 65536
    int nblk = B / 128;                          // 512

    k_build_U<<<1, 16>>>(vp);
    k_main<<<nblk, 256>>>(x, W, b, out);
    k_reduce<<<1, 256>>>(gamma, beta, nblk, 1.0f / (float)B);
    k_norm<<<(B + 255) / 256, 256>>>(out, B);
}

// round 2
// speedup vs baseline: 1.1297x; 1.1297x over previous
#include <cuda_runtime.h>
#include <cstdint>

// ---------------- device scratch (no allocations allowed) ----------------
__device__ __align__(16) float2 g_U[256];        // 16x16 variational unitary, row-major [i][j]
__device__ float  g_part[4096 * 8];              // per-block partial sums: [blk][0..3]=sum, [4..7]=sumsq
__device__ __align__(16) float g_scale[8];       // [0..3]=scale_w, [4..7]=shift_w

// ---------------- K1: build U (runs once per launch, 16 threads) ----------
struct cd { double re, im; };
__device__ __forceinline__ cd cmul(cd a, cd b) { return {a.re*b.re - a.im*b.im, a.re*b.im + a.im*b.re}; }
__device__ __forceinline__ cd cadd(cd a, cd b) { return {a.re + b.re, a.im + b.im}; }

__global__ void k_build_U(const float* __restrict__ vp) {
    int j = threadIdx.x;            // column index 0..15
    if (j >= 16) return;
    cd st[16];
    #pragma unroll
    for (int i = 0; i < 16; i++) st[i] = { (i == j) ? 1.0 : 0.0, 0.0 };

    for (int l = 0; l < 3; l++) {
        for (int w = 0; w < 4; w++) {
            double tx = vp[(l*4 + w)*3 + 0];
            double ty = vp[(l*4 + w)*3 + 1];
            double tz = vp[(l*4 + w)*3 + 2];
            double cx, sx, cy, sy, cz, sz;
            sincos(tx*0.5, &sx, &cx);
            sincos(ty*0.5, &sy, &cy);
            sincos(tz*0.5, &sz, &cz);
            cd M00{ cy*cx,  sy*sx }, M01{ -sy*cx, -cy*sx };
            cd M10{ sy*cx, -cy*sx }, M11{  cy*cx, -sy*sx };
            cd e0{ cz, -sz }, e1{ cz, sz };
            cd G00 = cmul(e0, M00), G01 = cmul(e0, M01);
            cd G10 = cmul(e1, M10), G11 = cmul(e1, M11);
            int mask = 8 >> w;      // wire w lives at bit (3-w)
            for (int i = 0; i < 16; i++) {
                if (i & mask) continue;
                cd s0 = st[i], s1 = st[i | mask];
                st[i]        = cadd(cmul(G00, s0), cmul(G01, s1));
                st[i | mask] = cadd(cmul(G10, s0), cmul(G11, s1));
            }
        }
        for (int w = 0; w < 3; w++) {    // CNOT chain
            int cm = 8 >> w, tm = 4 >> w;
            cd tmp[16];
            for (int i = 0; i < 16; i++) tmp[i] = st[(i & cm) ? (i ^ tm) : i];
            for (int i = 0; i < 16; i++) st[i] = tmp[i];
        }
    }
    for (int i = 0; i < 16; i++)
        g_U[i*16 + j] = make_float2((float)st[i].re, (float)st[i].im);
}

// ---------------- K2: coalesced stage -> pool -> circuit -> stats ---------
// Block: 256 threads, 16 samples. Stage rows 0..23 (672 floats = 168 float4
// per sample) into smem with batched float4 loads, then 16-lane groups do
// the pooling + feature + circuit math from smem.
#define SPB 16            // samples per block
#define F4S 168           // float4 per sample staged (24 rows x 28 cols / 4)
#define FLS 672           // floats per sample staged
#define TOT4 (SPB * F4S)  // 2688 float4 per block

__global__ __launch_bounds__(256) void k_main(
    const float* __restrict__ x, const float* __restrict__ W,
    const float* __restrict__ b, float* __restrict__ out)
{
    __shared__ float sm[SPB * FLS];       // 43008 B
    __shared__ float sPart[16][8];

    const int tid  = threadIdx.x;
    const int g    = tid >> 4;            // sample group 0..15
    const int p    = tid & 15;            // basis index 0..15

    // ---- stage: batched, coalesced float4 loads (MLP ~ 10) ----
    {
        const float4* xv = reinterpret_cast<const float4*>(x);
        float4* smv = reinterpret_cast<float4*>(sm);
        const long base = (long)blockIdx.x * SPB * 196;   // 196 f4 per raw sample
        float4 tmp[10];
        #pragma unroll
        for (int k = 0; k < 10; k++) {
            int j = tid + k*256;
            int s = j / F4S, r = j - s * F4S;
            tmp[k] = __ldcs(xv + base + s*196 + r);
        }
        float4 tl;
        if (tid < TOT4 - 2560) {                          // tail: 128 f4
            int j = 2560 + tid;
            int s = j / F4S, r = j - s * F4S;
            tl = __ldcs(xv + base + s*196 + r);
        }
        #pragma unroll
        for (int k = 0; k < 10; k++) smv[tid + k*256] = tmp[k];
        if (tid < TOT4 - 2560) smv[2560 + tid] = tl;
    }

    // ---- constants for this lane ----
    float Ur[16], Ui[16];
    {
        const float4* row = reinterpret_cast<const float4*>(g_U + p*16);
        #pragma unroll
        for (int q = 0; q < 8; q++) {
            float4 u = row[q];
            Ur[q*2+0] = u.x; Ui[q*2+0] = u.y;
            Ur[q*2+1] = u.z; Ui[q*2+1] = u.w;
        }
    }
    const float4 wrow = reinterpret_cast<const float4*>(W)[p];
    const float4 bv   = *reinterpret_cast<const float4*>(b);

    __syncthreads();

    // ---- pooled value for bin p of sample g: p = rb*4 + cb ----
    const int cb = p & 3, rb = p >> 2;
    const float* s0 = sm + g * FLS + (rb*6)*28 + cb*6;
    float v = 0.f;
    #pragma unroll
    for (int dr = 0; dr < 6; dr++)
        #pragma unroll
        for (int dc = 0; dc < 6; dc++)
            v += s0[dr*28 + dc];
    v *= (1.0f / 36.0f);

    // ---- feats = pooled @ W + b (butterfly within 16-lane group) ----
    float f0 = v*wrow.x, f1 = v*wrow.y, f2 = v*wrow.z, f3 = v*wrow.w;
    #pragma unroll
    for (int m = 1; m < 16; m <<= 1) {
        f0 += __shfl_xor_sync(0xffffffffu, f0, m);
        f1 += __shfl_xor_sync(0xffffffffu, f1, m);
        f2 += __shfl_xor_sync(0xffffffffu, f2, m);
        f3 += __shfl_xor_sync(0xffffffffu, f3, m);
    }
    f0 += bv.x; f1 += bv.y; f2 += bv.z; f3 += bv.w;

    // ---- encoded product state magnitudes ----
    float c0,s_0,c1,s_1,c2,s_2,c3,s_3;
    __sincosf(0.5f*f0, &s_0, &c0);
    __sincosf(0.5f*f1, &s_1, &c1);
    __sincosf(0.5f*f2, &s_2, &c2);
    __sincosf(0.5f*f3, &s_3, &c3);
    float w01[4] = { c0*c1, c0*s_1, s_0*c1, s_0*s_1 };
    float w23[4] = { c2*c3, c2*s_3, s_2*c3, s_2*s_3 };

    // ---- amp_p = sum_j U[p][j] * m_j * (-i)^popc(j) ----
    float ar = 0.f, ai = 0.f;
    #pragma unroll
    for (int j = 0; j < 16; j++) {
        float m = w01[j >> 2] * w23[j & 3];
        const int pm = __popc(j) & 3;
        if      (pm == 0) { ar += Ur[j]*m; ai += Ui[j]*m; }
        else if (pm == 1) { ar += Ui[j]*m; ai -= Ur[j]*m; }
        else if (pm == 2) { ar -= Ur[j]*m; ai -= Ui[j]*m; }
        else              { ar -= Ui[j]*m; ai += Ur[j]*m; }
    }
    float prob = ar*ar + ai*ai;

    // ---- expZ per wire: signed butterfly over 16 lanes ----
    float z[4];
    #pragma unroll
    for (int w = 0; w < 4; w++) {
        float vv = (p & (8 >> w)) ? -prob : prob;
        #pragma unroll
        for (int m = 1; m < 16; m <<= 1)
            vv += __shfl_xor_sync(0xffffffffu, vv, m);
        z[w] = vv;
    }

    if (p == 0) {
        long s = (long)blockIdx.x * SPB + g;
        reinterpret_cast<float4*>(out)[s] = make_float4(z[0], z[1], z[2], z[3]);
        sPart[g][0] = z[0];        sPart[g][1] = z[1];
        sPart[g][2] = z[2];        sPart[g][3] = z[3];
        sPart[g][4] = z[0]*z[0];   sPart[g][5] = z[1]*z[1];
        sPart[g][6] = z[2]*z[2];   sPart[g][7] = z[3]*z[3];
    }
    __syncthreads();
    if (tid < 8) {
        float t = 0.f;
        #pragma unroll
        for (int k = 0; k < 16; k++) t += sPart[k][tid];
        g_part[blockIdx.x * 8 + tid] = t;
    }
}

// ---------------- K3a: reduce partials -> batchnorm scale/shift ------------
__global__ void k_reduce(const float* __restrict__ gamma,
                         const float* __restrict__ beta,
                         int nblk, float invB)
{
    __shared__ float red[32][8];
    __shared__ float tot[8];
    int t = threadIdx.x;              // 256 threads
    int w = t & 7, g = t >> 3;        // 32 groups x 8 values
    float s = 0.f;
    for (int q = g; q < nblk; q += 32) s += g_part[q*8 + w];
    red[g][w] = s;
    __syncthreads();
    if (t < 8) {
        float tt = 0.f;
        #pragma unroll
        for (int g2 = 0; g2 < 32; g2++) tt += red[g2][t];
        tot[t] = tt;
    }
    __syncthreads();
    if (t < 4) {
        float mu  = tot[t] * invB;
        float var = tot[4 + t] * invB - mu*mu;   // biased var (ddof=0)
        float sc  = gamma[t] * rsqrtf(var + 1e-5f);
        g_scale[t]     = sc;
        g_scale[4 + t] = beta[t] - mu * sc;
    }
}

// ---------------- K3b: normalize in place (vectorized) ---------------------
__global__ void k_norm(float* __restrict__ out, int B)
{
    int i = blockIdx.x * blockDim.x + threadIdx.x;
    if (i >= B) return;
    float4 sc = *reinterpret_cast<const float4*>(&g_scale[0]);
    float4 sh = *reinterpret_cast<const float4*>(&g_scale[4]);
    float4 r  = reinterpret_cast<float4*>(out)[i];
    r.x = r.x*sc.x + sh.x;
    r.y = r.y*sc.y + sh.y;
    r.z = r.z*sc.z + sh.z;
    r.w = r.w*sc.w + sh.w;
    reinterpret_cast<float4*>(out)[i] = r;
}

// ---------------- launch ----------------------------------------------------
extern "C" void kernel_launch(void* const* d_in, const int* in_sizes, int n_in,
                              void* d_out, int out_size)
{
    const float* x     = (const float*)d_in[0];  // [B,1,28,28]
    const float* W     = (const float*)d_in[1];  // [16,4]
    const float* b     = (const float*)d_in[2];  // [4]
    const float* vp    = (const float*)d_in[3];  // [3,4,3]
    const float* gamma = (const float*)d_in[4];  // [4]
    const float* beta  = (const float*)d_in[5];  // [4]
    float* out = (float*)d_out;                  // [B,4]

    int B = in_sizes[0] / 784;                   // 65536
    int nblk = B / SPB;                          // 4096

    k_build_U<<<1, 16>>>(vp);
    k_main<<<nblk, 256>>>(x, W, b, out);
    k_reduce<<<1, 256>>>(gamma, beta, nblk, 1.0f / (float)B);
    k_norm<<<(B + 255) / 256, 256>>>(out, B);
}

// round 3
// speedup vs baseline: 2.5285x; 2.2382x over previous
#include <cuda_runtime.h>
#include <cstdint>

// ---------------- device scratch (no allocations allowed) ----------------
__device__ __align__(16) float2 g_U[256];        // 16x16 variational unitary, row-major [i][j]
__device__ float  g_part[4096 * 8];              // per-block partial sums: [blk][0..3]=sum, [4..7]=sumsq
__device__ __align__(16) float g_scale[8];       // [0..3]=scale_w, [4..7]=shift_w

// ---------------- K1: build U (fp32, runs once per launch, 16 threads) -----
struct cf { float re, im; };
__device__ __forceinline__ cf cmul(cf a, cf b) { return {a.re*b.re - a.im*b.im, a.re*b.im + a.im*b.re}; }
__device__ __forceinline__ cf cadd(cf a, cf b) { return {a.re + b.re, a.im + b.im}; }

__global__ void k_build_U(const float* __restrict__ vp) {
    int j = threadIdx.x;            // column index 0..15
    if (j >= 16) return;
    cf st[16];
    #pragma unroll
    for (int i = 0; i < 16; i++) st[i] = { (i == j) ? 1.0f : 0.0f, 0.0f };

    for (int l = 0; l < 3; l++) {
        for (int w = 0; w < 4; w++) {
            float tx = vp[(l*4 + w)*3 + 0];
            float ty = vp[(l*4 + w)*3 + 1];
            float tz = vp[(l*4 + w)*3 + 2];
            float cx, sx, cy, sy, cz, sz;
            sincosf(tx*0.5f, &sx, &cx);
            sincosf(ty*0.5f, &sy, &cy);
            sincosf(tz*0.5f, &sz, &cz);
            // M = RY * RX
            cf M00{ cy*cx,  sy*sx }, M01{ -sy*cx, -cy*sx };
            cf M10{ sy*cx, -cy*sx }, M11{  cy*cx, -sy*sx };
            // G = RZ * M  (RZ = diag(e^{-iz/2}, e^{+iz/2}))
            cf e0{ cz, -sz }, e1{ cz, sz };
            cf G00 = cmul(e0, M00), G01 = cmul(e0, M01);
            cf G10 = cmul(e1, M10), G11 = cmul(e1, M11);
            int mask = 8 >> w;      // wire w lives at bit (3-w)
            #pragma unroll
            for (int i = 0; i < 16; i++) {
                if (i & mask) continue;
                cf s0 = st[i], s1 = st[i | mask];
                st[i]        = cadd(cmul(G00, s0), cmul(G01, s1));
                st[i | mask] = cadd(cmul(G10, s0), cmul(G11, s1));
            }
        }
        for (int w = 0; w < 3; w++) {    // CNOT chain: ctrl bit (3-w), tgt bit (2-w)
            int cm = 8 >> w, tm = 4 >> w;
            cf tmp[16];
            #pragma unroll
            for (int i = 0; i < 16; i++) tmp[i] = st[(i & cm) ? (i ^ tm) : i];
            #pragma unroll
            for (int i = 0; i < 16; i++) st[i] = tmp[i];
        }
    }
    #pragma unroll
    for (int i = 0; i < 16; i++)
        g_U[i*16 + j] = make_float2(st[i].re, st[i].im);
}

// ---------------- K2: coalesced stage -> pool -> circuit -> stats ---------
#define SPB 16            // samples per block
#define F4S 168           // float4 per sample staged (24 rows x 28 cols / 4)
#define FLS 672           // floats per sample staged
#define TOT4 (SPB * F4S)  // 2688 float4 per block

__global__ __launch_bounds__(256) void k_main(
    const float* __restrict__ x, const float* __restrict__ W,
    const float* __restrict__ b, float* __restrict__ out)
{
    __shared__ float sm[SPB * FLS];       // 43008 B
    __shared__ float sPart[16][8];

    const int tid  = threadIdx.x;
    const int g    = tid >> 4;            // sample group 0..15
    const int p    = tid & 15;            // basis index 0..15

    // ---- stage: batched, coalesced float4 loads (MLP ~ 10) ----
    {
        const float4* xv = reinterpret_cast<const float4*>(x);
        float4* smv = reinterpret_cast<float4*>(sm);
        const long base = (long)blockIdx.x * SPB * 196;   // 196 f4 per raw sample
        float4 tmp[10];
        #pragma unroll
        for (int k = 0; k < 10; k++) {
            int j = tid + k*256;
            int s = j / F4S, r = j - s * F4S;
            tmp[k] = __ldcs(xv + base + s*196 + r);
        }
        float4 tl;
        if (tid < TOT4 - 2560) {                          // tail: 128 f4
            int j = 2560 + tid;
            int s = j / F4S, r = j - s * F4S;
            tl = __ldcs(xv + base + s*196 + r);
        }
        #pragma unroll
        for (int k = 0; k < 10; k++) smv[tid + k*256] = tmp[k];
        if (tid < TOT4 - 2560) smv[2560 + tid] = tl;
    }

    // ---- constants for this lane ----
    float Ur[16], Ui[16];
    {
        const float4* row = reinterpret_cast<const float4*>(g_U + p*16);
        #pragma unroll
        for (int q = 0; q < 8; q++) {
            float4 u = row[q];
            Ur[q*2+0] = u.x; Ui[q*2+0] = u.y;
            Ur[q*2+1] = u.z; Ui[q*2+1] = u.w;
        }
    }
    const float4 wrow = reinterpret_cast<const float4*>(W)[p];
    const float4 bv   = *reinterpret_cast<const float4*>(b);

    __syncthreads();

    // ---- pooled value for bin p of sample g: p = rb*4 + cb ----
    const int cb = p & 3, rb = p >> 2;
    const float* s0 = sm + g * FLS + (rb*6)*28 + cb*6;
    float v = 0.f;
    #pragma unroll
    for (int dr = 0; dr < 6; dr++)
        #pragma unroll
        for (int dc = 0; dc < 6; dc++)
            v += s0[dr*28 + dc];
    v *= (1.0f / 36.0f);

    // ---- feats = pooled @ W + b (butterfly within 16-lane group) ----
    float f0 = v*wrow.x, f1 = v*wrow.y, f2 = v*wrow.z, f3 = v*wrow.w;
    #pragma unroll
    for (int m = 1; m < 16; m <<= 1) {
        f0 += __shfl_xor_sync(0xffffffffu, f0, m);
        f1 += __shfl_xor_sync(0xffffffffu, f1, m);
        f2 += __shfl_xor_sync(0xffffffffu, f2, m);
        f3 += __shfl_xor_sync(0xffffffffu, f3, m);
    }
    f0 += bv.x; f1 += bv.y; f2 += bv.z; f3 += bv.w;

    // ---- encoded product state magnitudes ----
    float c0,s_0,c1,s_1,c2,s_2,c3,s_3;
    __sincosf(0.5f*f0, &s_0, &c0);
    __sincosf(0.5f*f1, &s_1, &c1);
    __sincosf(0.5f*f2, &s_2, &c2);
    __sincosf(0.5f*f3, &s_3, &c3);
    float w01[4] = { c0*c1, c0*s_1, s_0*c1, s_0*s_1 };
    float w23[4] = { c2*c3, c2*s_3, s_2*c3, s_2*s_3 };

    // ---- amp_p = sum_j U[p][j] * m_j * (-i)^popc(j) ----
    float ar = 0.f, ai = 0.f;
    #pragma unroll
    for (int j = 0; j < 16; j++) {
        float m = w01[j >> 2] * w23[j & 3];
        const int pm = __popc(j) & 3;
        if      (pm == 0) { ar += Ur[j]*m; ai += Ui[j]*m; }
        else if (pm == 1) { ar += Ui[j]*m; ai -= Ur[j]*m; }
        else if (pm == 2) { ar -= Ur[j]*m; ai -= Ui[j]*m; }
        else              { ar -= Ui[j]*m; ai += Ur[j]*m; }
    }
    float prob = ar*ar + ai*ai;

    // ---- expZ per wire: signed butterfly over 16 lanes ----
    float z[4];
    #pragma unroll
    for (int w = 0; w < 4; w++) {
        float vv = (p & (8 >> w)) ? -prob : prob;
        #pragma unroll
        for (int m = 1; m < 16; m <<= 1)
            vv += __shfl_xor_sync(0xffffffffu, vv, m);
        z[w] = vv;
    }

    if (p == 0) {
        long s = (long)blockIdx.x * SPB + g;
        reinterpret_cast<float4*>(out)[s] = make_float4(z[0], z[1], z[2], z[3]);
        sPart[g][0] = z[0];        sPart[g][1] = z[1];
        sPart[g][2] = z[2];        sPart[g][3] = z[3];
        sPart[g][4] = z[0]*z[0];   sPart[g][5] = z[1]*z[1];
        sPart[g][6] = z[2]*z[2];   sPart[g][7] = z[3]*z[3];
    }
    __syncthreads();
    if (tid < 8) {
        float t = 0.f;
        #pragma unroll
        for (int k = 0; k < 16; k++) t += sPart[k][tid];
        g_part[blockIdx.x * 8 + tid] = t;
    }
}

// ---------------- K3a: reduce partials -> batchnorm scale/shift ------------
__global__ void k_reduce(const float* __restrict__ gamma,
                         const float* __restrict__ beta,
                         int nblk, float invB)
{
    __shared__ float red[32][8];
    __shared__ float tot[8];
    int t = threadIdx.x;              // 256 threads
    int w = t & 7, g = t >> 3;        // 32 groups x 8 values
    float s = 0.f;
    for (int q = g; q < nblk; q += 32) s += g_part[q*8 + w];
    red[g][w] = s;
    __syncthreads();
    if (t < 8) {
        float tt = 0.f;
        #pragma unroll
        for (int g2 = 0; g2 < 32; g2++) tt += red[g2][t];
        tot[t] = tt;
    }
    __syncthreads();
    if (t < 4) {
        float mu  = tot[t] * invB;
        float var = tot[4 + t] * invB - mu*mu;   // biased var (ddof=0)
        float sc  = gamma[t] * rsqrtf(var + 1e-5f);
        g_scale[t]     = sc;
        g_scale[4 + t] = beta[t] - mu * sc;
    }
}

// ---------------- K3b: normalize in place (vectorized) ---------------------
__global__ void k_norm(float* __restrict__ out, int B)
{
    int i = blockIdx.x * blockDim.x + threadIdx.x;
    if (i >= B) return;
    float4 sc = *reinterpret_cast<const float4*>(&g_scale[0]);
    float4 sh = *reinterpret_cast<const float4*>(&g_scale[4]);
    float4 r  = reinterpret_cast<float4*>(out)[i];
    r.x = r.x*sc.x + sh.x;
    r.y = r.y*sc.y + sh.y;
    r.z = r.z*sc.z + sh.z;
    r.w = r.w*sc.w + sh.w;
    reinterpret_cast<float4*>(out)[i] = r;
}

// ---------------- launch ----------------------------------------------------
extern "C" void kernel_launch(void* const* d_in, const int* in_sizes, int n_in,
                              void* d_out, int out_size)
{
    const float* x     = (const float*)d_in[0];  // [B,1,28,28]
    const float* W     = (const float*)d_in[1];  // [16,4]
    const float* b     = (const float*)d_in[2];  // [4]
    const float* vp    = (const float*)d_in[3];  // [3,4,3]
    const float* gamma = (const float*)d_in[4];  // [4]
    const float* beta  = (const float*)d_in[5];  // [4]
    float* out = (float*)d_out;                  // [B,4]

    int B = in_sizes[0] / 784;                   // 65536
    int nblk = B / SPB;                          // 4096

    k_build_U<<<1, 16>>>(vp);
    k_main<<<nblk, 256>>>(x, W, b, out);
    k_reduce<<<1, 256>>>(gamma, beta, nblk, 1.0f / (float)B);
    k_norm<<<(B + 255) / 256, 256>>>(out, B);
}

// round 4
// speedup vs baseline: 3.4027x; 1.3458x over previous
#include <cuda_runtime.h>
#include <cstdint>

// ---------------- config ----------------
#define SPT  8                 // samples per tile
#define TPB  16                // tiles per block  -> 128 samples per block
#define FLS  672               // floats staged per sample (rows 0..23 x 28)
#define F4T  (SPT * 168)       // float4 per tile = 1344

// ---------------- device scratch (no allocations allowed) ----------------
__device__ float g_part[1024 * 8];   // per-block sums [blk][0..3]=S, [4..7]=Q

// ---------------- helpers ----------------
__device__ __forceinline__ void cp16(float4* dst_smem, const float4* src_gmem) {
    unsigned d = (unsigned)__cvta_generic_to_shared(dst_smem);
    asm volatile("cp.async.cg.shared.global [%0], [%1], 16;\n"
                 :: "r"(d), "l"(src_gmem));
}

struct cf { float re, im; };
__device__ __forceinline__ cf cmul(cf a, cf b) { return {a.re*b.re - a.im*b.im, a.re*b.im + a.im*b.re}; }
__device__ __forceinline__ cf cadd(cf a, cf b) { return {a.re + b.re, a.im + b.im}; }

// ---------------- K1: fused main -------------------------------------------
// 256 threads = 8 warps. Warp w handles sample-slot w of each tile (both
// 16-lane halves compute redundantly; lane 0 commits). Double-buffered
// cp.async staging of 8-sample tiles.
__global__ __launch_bounds__(256) void k_main(
    const float* __restrict__ x, const float* __restrict__ W,
    const float* __restrict__ b, const float* __restrict__ vp,
    float* __restrict__ out)
{
    __shared__ float  sm[2][SPT * FLS];   // 43008 B
    __shared__ float2 sU[256];            // transposed: sU[j*16+p] = U[p][j]
    __shared__ float  sPart[8][8];

    const int tid  = threadIdx.x;
    const int w    = tid >> 5;            // warp id = sample slot in tile
    const int lane = tid & 31;
    const int p    = lane & 15;           // basis index

    const float4* xv = reinterpret_cast<const float4*>(x);
    const long blkTileBase = (long)blockIdx.x * TPB;

    // ---- issue tile 0 loads ----
    {
        const float4* src = xv + (blkTileBase * SPT) * 196;
        float4* dst = reinterpret_cast<float4*>(sm[0]);
        #pragma unroll
        for (int k = 0; k < 5; k++) {
            int j = tid + k*256;
            int s = j / 168, r = j - s*168;
            cp16(dst + j, src + s*196 + r);
        }
        if (tid < F4T - 1280) {
            int j = 1280 + tid;
            int s = j / 168, r = j - s*168;
            cp16(dst + j, src + s*196 + r);
        }
        asm volatile("cp.async.commit_group;\n");
    }

    // ---- build U (warp 0, 16 threads) while tile 0 flies ----
    if (tid < 16) {
        const int j = tid;                // column index
        cf st[16];
        #pragma unroll
        for (int i = 0; i < 16; i++) st[i] = { (i == j) ? 1.0f : 0.0f, 0.0f };
        for (int l = 0; l < 3; l++) {
            for (int ww = 0; ww < 4; ww++) {
                float tx = vp[(l*4 + ww)*3 + 0];
                float ty = vp[(l*4 + ww)*3 + 1];
                float tz = vp[(l*4 + ww)*3 + 2];
                float cx, sx, cy, sy, cz, sz;
                sincosf(tx*0.5f, &sx, &cx);
                sincosf(ty*0.5f, &sy, &cy);
                sincosf(tz*0.5f, &sz, &cz);
                cf M00{ cy*cx,  sy*sx }, M01{ -sy*cx, -cy*sx };
                cf M10{ sy*cx, -cy*sx }, M11{  cy*cx, -sy*sx };
                cf e0{ cz, -sz }, e1{ cz, sz };
                cf G00 = cmul(e0, M00), G01 = cmul(e0, M01);
                cf G10 = cmul(e1, M10), G11 = cmul(e1, M11);
                int mask = 8 >> ww;
                #pragma unroll
                for (int i = 0; i < 16; i++) {
                    if (i & mask) continue;
                    cf s0 = st[i], s1 = st[i | mask];
                    st[i]        = cadd(cmul(G00, s0), cmul(G01, s1));
                    st[i | mask] = cadd(cmul(G10, s0), cmul(G11, s1));
                }
            }
            for (int ww = 0; ww < 3; ww++) {   // CNOT chain
                int cm = 8 >> ww, tm = 4 >> ww;
                cf tmp[16];
                #pragma unroll
                for (int i = 0; i < 16; i++) tmp[i] = st[(i & cm) ? (i ^ tm) : i];
                #pragma unroll
                for (int i = 0; i < 16; i++) st[i] = tmp[i];
            }
        }
        #pragma unroll
        for (int i = 0; i < 16; i++)
            sU[j*16 + i] = make_float2(st[i].re, st[i].im);   // transposed store
    }

    const float4 wrow = reinterpret_cast<const float4*>(W)[p];
    const float4 bv   = *reinterpret_cast<const float4*>(b);

    float runS0=0, runS1=0, runS2=0, runS3=0;
    float runQ0=0, runQ1=0, runQ2=0, runQ3=0;

    const int cb = p & 3, rb = p >> 2;
    const int poolOff = w*FLS + (rb*6)*28 + cb*6;

    for (int t = 0; t < TPB; t++) {
        // prefetch tile t+1 into the other buffer
        if (t + 1 < TPB) {
            const float4* src = xv + ((blkTileBase + t + 1) * SPT) * 196;
            float4* dst = reinterpret_cast<float4*>(sm[(t+1) & 1]);
            #pragma unroll
            for (int k = 0; k < 5; k++) {
                int j = tid + k*256;
                int s = j / 168, r = j - s*168;
                cp16(dst + j, src + s*196 + r);
            }
            if (tid < F4T - 1280) {
                int j = 1280 + tid;
                int s = j / 168, r = j - s*168;
                cp16(dst + j, src + s*196 + r);
            }
            asm volatile("cp.async.commit_group;\n");
            asm volatile("cp.async.wait_group 1;\n");
        } else {
            asm volatile("cp.async.wait_group 0;\n");
        }
        __syncthreads();

        // ---- pooling for bin p of sample-slot w ----
        const float* s0 = sm[t & 1] + poolOff;
        float v = 0.f;
        #pragma unroll
        for (int dr = 0; dr < 6; dr++)
            #pragma unroll
            for (int dc = 0; dc < 6; dc++)
                v += s0[dr*28 + dc];
        v *= (1.0f / 36.0f);

        // ---- feats = pooled @ W + b (butterfly within 16-lane group) ----
        float f0 = v*wrow.x, f1 = v*wrow.y, f2 = v*wrow.z, f3 = v*wrow.w;
        #pragma unroll
        for (int m = 1; m < 16; m <<= 1) {
            f0 += __shfl_xor_sync(0xffffffffu, f0, m);
            f1 += __shfl_xor_sync(0xffffffffu, f1, m);
            f2 += __shfl_xor_sync(0xffffffffu, f2, m);
            f3 += __shfl_xor_sync(0xffffffffu, f3, m);
        }
        f0 += bv.x; f1 += bv.y; f2 += bv.z; f3 += bv.w;

        // ---- encoded product-state magnitudes ----
        float c0,s_0,c1,s_1,c2,s_2,c3,s_3;
        __sincosf(0.5f*f0, &s_0, &c0);
        __sincosf(0.5f*f1, &s_1, &c1);
        __sincosf(0.5f*f2, &s_2, &c2);
        __sincosf(0.5f*f3, &s_3, &c3);
        float w01[4] = { c0*c1, c0*s_1, s_0*c1, s_0*s_1 };
        float w23[4] = { c2*c3, c2*s_3, s_2*c3, s_2*s_3 };

        // ---- amp_p = sum_j U[p][j] * m_j * (-i)^popc(j), U from smem ----
        float ar = 0.f, ai = 0.f;
        #pragma unroll
        for (int j = 0; j < 16; j++) {
            float m = w01[j >> 2] * w23[j & 3];
            float2 u = sU[j*16 + p];
            const int pm = __popc(j) & 3;
            if      (pm == 0) { ar += u.x*m; ai += u.y*m; }
            else if (pm == 1) { ar += u.y*m; ai -= u.x*m; }
            else if (pm == 2) { ar -= u.x*m; ai -= u.y*m; }
            else              { ar -= u.y*m; ai += u.x*m; }
        }
        float prob = ar*ar + ai*ai;

        // ---- expZ per wire: signed butterfly over 16 lanes ----
        float z[4];
        #pragma unroll
        for (int ww = 0; ww < 4; ww++) {
            float vv = (p & (8 >> ww)) ? -prob : prob;
            #pragma unroll
            for (int m = 1; m < 16; m <<= 1)
                vv += __shfl_xor_sync(0xffffffffu, vv, m);
            z[ww] = vv;
        }

        if (lane == 0) {
            long s = (blkTileBase + t) * SPT + w;
            reinterpret_cast<float4*>(out)[s] = make_float4(z[0], z[1], z[2], z[3]);
            runS0 += z[0]; runS1 += z[1]; runS2 += z[2]; runS3 += z[3];
            runQ0 += z[0]*z[0]; runQ1 += z[1]*z[1];
            runQ2 += z[2]*z[2]; runQ3 += z[3]*z[3];
        }
        __syncthreads();   // protect buffer reuse by next prefetch
    }

    if (lane == 0) {
        sPart[w][0] = runS0; sPart[w][1] = runS1;
        sPart[w][2] = runS2; sPart[w][3] = runS3;
        sPart[w][4] = runQ0; sPart[w][5] = runQ1;
        sPart[w][6] = runQ2; sPart[w][7] = runQ3;
    }
    __syncthreads();
    if (tid < 8) {
        float t = 0.f;
        #pragma unroll
        for (int k = 0; k < 8; k++) t += sPart[k][tid];
        g_part[blockIdx.x * 8 + tid] = t;
    }
}

// ---------------- K2: fused reduce + normalize ------------------------------
// Every block redundantly reduces the per-block partials (L2-resident),
// computes scale/shift, then normalizes its slice of out.
__global__ __launch_bounds__(256) void k_fin(
    const float* __restrict__ gamma, const float* __restrict__ beta,
    float* __restrict__ out, int nblk, float invB, int B)
{
    __shared__ float sRed[32][8];
    __shared__ float tot[8];
    __shared__ float sc[8];

    int tid = threadIdx.x;
    int ch = tid & 7, grp = tid >> 3;
    float s = 0.f;
    for (int q = grp; q < nblk; q += 32) s += g_part[q*8 + ch];
    sRed[grp][ch] = s;
    __syncthreads();
    if (tid < 8) {
        float tt = 0.f;
        #pragma unroll
        for (int g2 = 0; g2 < 32; g2++) tt += sRed[g2][tid];
        tot[tid] = tt;
    }
    __syncthreads();
    if (tid < 4) {
        float mu  = tot[tid] * invB;
        float var = tot[4 + tid] * invB - mu*mu;   // biased var
        float scw = gamma[tid] * rsqrtf(var + 1e-5f);
        sc[tid]     = scw;
        sc[4 + tid] = beta[tid] - mu * scw;
    }
    __syncthreads();

    int i = blockIdx.x * blockDim.x + tid;
    if (i < B) {
        float4 scv = *reinterpret_cast<const float4*>(&sc[0]);
        float4 shv = *reinterpret_cast<const float4*>(&sc[4]);
        float4 r   = reinterpret_cast<float4*>(out)[i];
        r.x = r.x*scv.x + shv.x;
        r.y = r.y*scv.y + shv.y;
        r.z = r.z*scv.z + shv.z;
        r.w = r.w*scv.w + shv.w;
        reinterpret_cast<float4*>(out)[i] = r;
    }
}

// ---------------- launch ----------------------------------------------------
extern "C" void kernel_launch(void* const* d_in, const int* in_sizes, int n_in,
                              void* d_out, int out_size)
{
    const float* x     = (const float*)d_in[0];  // [B,1,28,28]
    const float* W     = (const float*)d_in[1];  // [16,4]
    const float* b     = (const float*)d_in[2];  // [4]
    const float* vp    = (const float*)d_in[3];  // [3,4,3]
    const float* gamma = (const float*)d_in[4];  // [4]
    const float* beta  = (const float*)d_in[5];  // [4]
    float* out = (float*)d_out;                  // [B,4]

    int B = in_sizes[0] / 784;                   // 65536
    int nblk = B / (TPB * SPT);                  // 512 blocks, 128 samples each

    k_main<<<nblk, 256>>>(x, W, b, vp, out);
    k_fin<<<(B + 255) / 256, 256>>>(gamma, beta, out, nblk, 1.0f / (float)B, B);
}

// round 5
// speedup vs baseline: 3.6811x; 1.0818x over previous
#include <cuda_runtime.h>
#include <cstdint>

// ---------------- config ----------------
#define STEPS 8                // sample-pairs per warp
#define WPB   4                // warps per block
#define SPB   (WPB * 2 * STEPS)   // 64 samples per block
#define F4P   336              // float4 per pair staged (2 x 168)

// ---------------- device scratch ----------------
__device__ float g_part[1024 * 8];   // [blk][0..3]=S, [4..7]=Q

__device__ __forceinline__ void cp16(float4* dst_smem, const float4* src_gmem) {
    unsigned d = (unsigned)__cvta_generic_to_shared(dst_smem);
    asm volatile("cp.async.cg.shared.global [%0], [%1], 16;\n"
                 :: "r"(d), "l"(src_gmem));
}

struct cf { float re, im; };
__device__ __forceinline__ cf cmul(cf a, cf b) { return {a.re*b.re - a.im*b.im, a.re*b.im + a.im*b.re}; }
__device__ __forceinline__ cf cadd(cf a, cf b) { return {a.re + b.re, a.im + b.im}; }

// ---------------- K1: fused main (warp-autonomous pipelines) ---------------
__global__ __launch_bounds__(128) void k_main(
    const float* __restrict__ x, const float* __restrict__ W,
    const float* __restrict__ b, const float* __restrict__ vp,
    float* __restrict__ out)
{
    __shared__ float4 smv[2][WPB][F4P];    // 43008 B, per-warp double buffers
    __shared__ float2 sU[256];             // transposed: sU[j*16+p] = U[p][j]
    __shared__ float  sPart[WPB][8];

    const int tid  = threadIdx.x;
    const int w    = tid >> 5;
    const int lane = tid & 31;
    const int h    = lane >> 4;            // sample within pair
    const int p    = lane & 15;            // basis index

    const float4* xv = reinterpret_cast<const float4*>(x);
    const long warpSampleBase = (long)blockIdx.x * SPB + w * (2 * STEPS);

    // ---- issue pair 0 loads for this warp ----
    {
        long s0 = warpSampleBase;
        float4* dst = &smv[0][w][0];
        #pragma unroll
        for (int k = 0; k < 10; k++) {
            int idx = k*32 + lane;
            int so = (idx >= 168);
            cp16(dst + idx, xv + (s0 + so)*196 + (idx - so*168));
        }
        if (lane < 16) {
            int idx = 320 + lane;
            cp16(dst + idx, xv + (s0 + 1)*196 + (idx - 168));
        }
        asm volatile("cp.async.commit_group;\n");
    }

    // ---- warp 0 builds U while pair-0 loads fly ----
    if (tid < 16) {
        const int j = tid;
        cf st[16];
        #pragma unroll
        for (int i = 0; i < 16; i++) st[i] = { (i == j) ? 1.0f : 0.0f, 0.0f };
        for (int l = 0; l < 3; l++) {
            for (int ww = 0; ww < 4; ww++) {
                float tx = vp[(l*4 + ww)*3 + 0];
                float ty = vp[(l*4 + ww)*3 + 1];
                float tz = vp[(l*4 + ww)*3 + 2];
                float cx, sx, cy, sy, cz, sz;
                sincosf(tx*0.5f, &sx, &cx);
                sincosf(ty*0.5f, &sy, &cy);
                sincosf(tz*0.5f, &sz, &cz);
                cf M00{ cy*cx,  sy*sx }, M01{ -sy*cx, -cy*sx };
                cf M10{ sy*cx, -cy*sx }, M11{  cy*cx, -sy*sx };
                cf e0{ cz, -sz }, e1{ cz, sz };
                cf G00 = cmul(e0, M00), G01 = cmul(e0, M01);
                cf G10 = cmul(e1, M10), G11 = cmul(e1, M11);
                int mask = 8 >> ww;
                #pragma unroll
                for (int i = 0; i < 16; i++) {
                    if (i & mask) continue;
                    cf a0 = st[i], a1 = st[i | mask];
                    st[i]        = cadd(cmul(G00, a0), cmul(G01, a1));
                    st[i | mask] = cadd(cmul(G10, a0), cmul(G11, a1));
                }
            }
            for (int ww = 0; ww < 3; ww++) {   // CNOT chain
                int cm = 8 >> ww, tm = 4 >> ww;
                cf tmp[16];
                #pragma unroll
                for (int i = 0; i < 16; i++) tmp[i] = st[(i & cm) ? (i ^ tm) : i];
                #pragma unroll
                for (int i = 0; i < 16; i++) st[i] = tmp[i];
            }
        }
        #pragma unroll
        for (int i = 0; i < 16; i++)
            sU[j*16 + i] = make_float2(st[i].re, st[i].im);
    }
    __syncthreads();     // only block-wide barrier: publish sU

    // ---- per-lane constants ----
    float Ur[16], Ui[16];
    #pragma unroll
    for (int j = 0; j < 16; j++) {
        float2 u = sU[j*16 + p];
        Ur[j] = u.x; Ui[j] = u.y;
    }
    const float4 wrow = reinterpret_cast<const float4*>(W)[p];
    const float4 bv   = *reinterpret_cast<const float4*>(b);

    float runS0=0, runS1=0, runS2=0, runS3=0;
    float runQ0=0, runQ1=0, runQ2=0, runQ3=0;

    const int cb = p & 3, rb = p >> 2;
    const int poolOff = h*672 + rb*168 + cb*6;

    for (int t = 0; t < STEPS; t++) {
        if (t + 1 < STEPS) {
            long s0 = warpSampleBase + (t + 1) * 2;
            float4* dst = &smv[(t+1) & 1][w][0];
            #pragma unroll
            for (int k = 0; k < 10; k++) {
                int idx = k*32 + lane;
                int so = (idx >= 168);
                cp16(dst + idx, xv + (s0 + so)*196 + (idx - so*168));
            }
            if (lane < 16) {
                int idx = 320 + lane;
                cp16(dst + idx, xv + (s0 + 1)*196 + (idx - 168));
            }
            asm volatile("cp.async.commit_group;\n");
            asm volatile("cp.async.wait_group 1;\n");
        } else {
            asm volatile("cp.async.wait_group 0;\n");
        }
        __syncwarp();

        // ---- pooling: lane (h,p) -> bin p of sample h ----
        const float* s0f = reinterpret_cast<const float*>(&smv[t & 1][w][0]) + poolOff;
        float v = 0.f;
        #pragma unroll
        for (int dr = 0; dr < 6; dr++)
            #pragma unroll
            for (int dc = 0; dc < 6; dc++)
                v += s0f[dr*28 + dc];
        v *= (1.0f / 36.0f);

        // ---- feats = pooled @ W + b (butterfly within 16-lane half) ----
        float f0 = v*wrow.x, f1 = v*wrow.y, f2 = v*wrow.z, f3 = v*wrow.w;
        #pragma unroll
        for (int m = 1; m < 16; m <<= 1) {
            f0 += __shfl_xor_sync(0xffffffffu, f0, m);
            f1 += __shfl_xor_sync(0xffffffffu, f1, m);
            f2 += __shfl_xor_sync(0xffffffffu, f2, m);
            f3 += __shfl_xor_sync(0xffffffffu, f3, m);
        }
        f0 += bv.x; f1 += bv.y; f2 += bv.z; f3 += bv.w;

        // ---- encoded product-state magnitudes ----
        float c0,s_0,c1,s_1,c2,s_2,c3,s_3;
        __sincosf(0.5f*f0, &s_0, &c0);
        __sincosf(0.5f*f1, &s_1, &c1);
        __sincosf(0.5f*f2, &s_2, &c2);
        __sincosf(0.5f*f3, &s_3, &c3);
        float w01[4] = { c0*c1, c0*s_1, s_0*c1, s_0*s_1 };
        float w23[4] = { c2*c3, c2*s_3, s_2*c3, s_2*s_3 };

        // ---- amp_p = sum_j U[p][j] * m_j * (-i)^popc(j) ----
        float ar = 0.f, ai = 0.f;
        #pragma unroll
        for (int j = 0; j < 16; j++) {
            float m = w01[j >> 2] * w23[j & 3];
            const int pm = __popc(j) & 3;
            if      (pm == 0) { ar += Ur[j]*m; ai += Ui[j]*m; }
            else if (pm == 1) { ar += Ui[j]*m; ai -= Ur[j]*m; }
            else if (pm == 2) { ar -= Ur[j]*m; ai -= Ui[j]*m; }
            else              { ar -= Ui[j]*m; ai += Ur[j]*m; }
        }
        float prob = ar*ar + ai*ai;

        // ---- expZ: 4-stage Walsh-Hadamard butterfly over the 16-lane half ----
        float v4 = prob;
        #pragma unroll
        for (int m = 1; m < 16; m <<= 1) {
            float o = __shfl_xor_sync(0xffffffffu, v4, m);
            v4 = (p & m) ? (o - v4) : (v4 + o);
        }
        // lane p now holds WHT[p]; z_w lives at p = 8>>w
        const int hb = h << 4;
        float z0 = __shfl_sync(0xffffffffu, v4, hb + 8);
        float z1 = __shfl_sync(0xffffffffu, v4, hb + 4);
        float z2 = __shfl_sync(0xffffffffu, v4, hb + 2);
        float z3 = __shfl_sync(0xffffffffu, v4, hb + 1);

        if (p == 0) {
            long s = warpSampleBase + t*2 + h;
            reinterpret_cast<float4*>(out)[s] = make_float4(z0, z1, z2, z3);
            runS0 += z0; runS1 += z1; runS2 += z2; runS3 += z3;
            runQ0 += z0*z0; runQ1 += z1*z1; runQ2 += z2*z2; runQ3 += z3*z3;
        }
    }

    // combine the two halves' stats (lanes 0 and 16 hold them)
    runS0 += __shfl_xor_sync(0xffffffffu, runS0, 16);
    runS1 += __shfl_xor_sync(0xffffffffu, runS1, 16);
    runS2 += __shfl_xor_sync(0xffffffffu, runS2, 16);
    runS3 += __shfl_xor_sync(0xffffffffu, runS3, 16);
    runQ0 += __shfl_xor_sync(0xffffffffu, runQ0, 16);
    runQ1 += __shfl_xor_sync(0xffffffffu, runQ1, 16);
    runQ2 += __shfl_xor_sync(0xffffffffu, runQ2, 16);
    runQ3 += __shfl_xor_sync(0xffffffffu, runQ3, 16);

    if (lane == 0) {
        sPart[w][0] = runS0; sPart[w][1] = runS1;
        sPart[w][2] = runS2; sPart[w][3] = runS3;
        sPart[w][4] = runQ0; sPart[w][5] = runQ1;
        sPart[w][6] = runQ2; sPart[w][7] = runQ3;
    }
    __syncthreads();
    if (tid < 8) {
        float t = sPart[0][tid] + sPart[1][tid] + sPart[2][tid] + sPart[3][tid];
        g_part[blockIdx.x * 8 + tid] = t;
    }
}

// ---------------- K2: fused reduce + normalize ------------------------------
__global__ __launch_bounds__(1024) void k_fin(
    const float* __restrict__ gamma, const float* __restrict__ beta,
    float* __restrict__ out, int nblk, float invB, int B)
{
    __shared__ float sRed[128][8];
    __shared__ float tot[8];
    __shared__ float sc[8];

    int tid = threadIdx.x;                // 1024 threads
    int ch = tid & 7, grp = tid >> 3;     // 128 groups x 8 channels
    float s = 0.f;
    #pragma unroll 4
    for (int q = grp; q < nblk; q += 128) s += g_part[q*8 + ch];
    sRed[grp][ch] = s;
    __syncthreads();
    if (tid < 8) {
        float tt = 0.f;
        #pragma unroll
        for (int g2 = 0; g2 < 128; g2++) tt += sRed[g2][tid];
        tot[tid] = tt;
    }
    __syncthreads();
    if (tid < 4) {
        float mu  = tot[tid] * invB;
        float var = tot[4 + tid] * invB - mu*mu;   // biased var
        float scw = gamma[tid] * rsqrtf(var + 1e-5f);
        sc[tid]     = scw;
        sc[4 + tid] = beta[tid] - mu * scw;
    }
    __syncthreads();

    int i = blockIdx.x * blockDim.x + tid;
    if (i < B) {
        float4 scv = *reinterpret_cast<const float4*>(&sc[0]);
        float4 shv = *reinterpret_cast<const float4*>(&sc[4]);
        float4 r   = reinterpret_cast<float4*>(out)[i];
        r.x = r.x*scv.x + shv.x;
        r.y = r.y*scv.y + shv.y;
        r.z = r.z*scv.z + shv.z;
        r.w = r.w*scv.w + shv.w;
        reinterpret_cast<float4*>(out)[i] = r;
    }
}

// ---------------- launch ----------------------------------------------------
extern "C" void kernel_launch(void* const* d_in, const int* in_sizes, int n_in,
                              void* d_out, int out_size)
{
    const float* x     = (const float*)d_in[0];  // [B,1,28,28]
    const float* W     = (const float*)d_in[1];  // [16,4]
    const float* b     = (const float*)d_in[2];  // [4]
    const float* vp    = (const float*)d_in[3];  // [3,4,3]
    const float* gamma = (const float*)d_in[4];  // [4]
    const float* beta  = (const float*)d_in[5];  // [4]
    float* out = (float*)d_out;                  // [B,4]

    int B = in_sizes[0] / 784;                   // 65536
    int nblk = B / SPB;                          // 1024 blocks, 64 samples each

    k_main<<<nblk, 128>>>(x, W, b, vp, out);
    k_fin<<<(B + 1023) / 1024, 1024>>>(gamma, beta, out, nblk, 1.0f / (float)B, B);
}

// round 6
// speedup vs baseline: 4.0065x; 1.0884x over previous
#include <cuda_runtime.h>
#include <cstdint>

// ---------------- config ----------------
#define GRID   512             // persistent blocks (<= 592 resident guaranteed)
#define WPB    4               // warps per block
#define PAIRS  16              // sample-pairs per warp (2 chunks x 8)
#define SPCH   64              // samples per chunk
#define F4P    336             // float4 per pair staged (2 x 168)

// ---------------- device scratch ----------------
__device__ float    g_part[GRID * 8];    // [blk][0..3]=S, [4..7]=Q
__device__ float    g_scale[8];          // scale/shift
__device__ unsigned g_cnt  = 0;          // monotonic ticket counter
__device__ unsigned g_flag = 0;          // monotonic epoch flag

__device__ __forceinline__ void cp16(float4* dst_smem, const float4* src_gmem) {
    unsigned d = (unsigned)__cvta_generic_to_shared(dst_smem);
    asm volatile("cp.async.cg.shared.global [%0], [%1], 16;\n"
                 :: "r"(d), "l"(src_gmem));
}

struct cf { float re, im; };
__device__ __forceinline__ cf cmul(cf a, cf b) { return {a.re*b.re - a.im*b.im, a.re*b.im + a.im*b.re}; }
__device__ __forceinline__ cf cadd(cf a, cf b) { return {a.re + b.re, a.im + b.im}; }

// ---------------- the one kernel --------------------------------------------
__global__ __launch_bounds__(128, 4) void k_all(
    const float* __restrict__ x, const float* __restrict__ W,
    const float* __restrict__ b, const float* __restrict__ vp,
    const float* __restrict__ gamma, const float* __restrict__ beta,
    float* __restrict__ out, int B)
{
    __shared__ float4 smv[2][WPB][F4P];    // 43008 B, per-warp double buffers
    __shared__ float2 sU[256];             // sU[j*16+p] = U[p][j]
    __shared__ float  sPart[WPB][8];
    __shared__ float  sScale[8];

    const int tid  = threadIdx.x;
    const int w    = tid >> 5;
    const int lane = tid & 31;
    const int h    = lane >> 4;            // sample within pair
    const int p    = lane & 15;            // basis index
    const int bid  = blockIdx.x;

    const unsigned epoch = *(volatile unsigned*)&g_flag;   // stable at entry

    const float4* xv = reinterpret_cast<const float4*>(x);
    const long c0 = (long)bid, c1 = (long)bid + GRID;      // this block's chunks

    // sample index of pair q for this warp
    auto samp = [&](int q) -> long {
        return ((q < 8) ? c0 : c1) * SPCH + w * 16 + (q & 7) * 2;
    };
    auto issue = [&](int q, int buf) {
        long s0 = samp(q);
        float4* dst = &smv[buf][w][0];
        #pragma unroll
        for (int k = 0; k < 10; k++) {
            int idx = k*32 + lane;
            int so = (idx >= 168);
            cp16(dst + idx, xv + (s0 + so)*196 + (idx - so*168));
        }
        if (lane < 16) {
            int idx = 320 + lane;
            cp16(dst + idx, xv + (s0 + 1)*196 + (idx - 168));
        }
        asm volatile("cp.async.commit_group;\n");
    };

    issue(0, 0);

    // ---- warp 0 builds U while pair-0 loads fly ----
    if (tid < 16) {
        const int j = tid;
        cf st[16];
        #pragma unroll
        for (int i = 0; i < 16; i++) st[i] = { (i == j) ? 1.0f : 0.0f, 0.0f };
        for (int l = 0; l < 3; l++) {
            for (int ww = 0; ww < 4; ww++) {
                float tx = vp[(l*4 + ww)*3 + 0];
                float ty = vp[(l*4 + ww)*3 + 1];
                float tz = vp[(l*4 + ww)*3 + 2];
                float cx, sx, cy, sy, cz, sz;
                sincosf(tx*0.5f, &sx, &cx);
                sincosf(ty*0.5f, &sy, &cy);
                sincosf(tz*0.5f, &sz, &cz);
                cf M00{ cy*cx,  sy*sx }, M01{ -sy*cx, -cy*sx };
                cf M10{ sy*cx, -cy*sx }, M11{  cy*cx, -sy*sx };
                cf e0{ cz, -sz }, e1{ cz, sz };
                cf G00 = cmul(e0, M00), G01 = cmul(e0, M01);
                cf G10 = cmul(e1, M10), G11 = cmul(e1, M11);
                int mask = 8 >> ww;
                #pragma unroll
                for (int i = 0; i < 16; i++) {
                    if (i & mask) continue;
                    cf a0 = st[i], a1 = st[i | mask];
                    st[i]        = cadd(cmul(G00, a0), cmul(G01, a1));
                    st[i | mask] = cadd(cmul(G10, a0), cmul(G11, a1));
                }
            }
            for (int ww = 0; ww < 3; ww++) {   // CNOT chain
                int cm = 8 >> ww, tm = 4 >> ww;
                cf tmp[16];
                #pragma unroll
                for (int i = 0; i < 16; i++) tmp[i] = st[(i & cm) ? (i ^ tm) : i];
                #pragma unroll
                for (int i = 0; i < 16; i++) st[i] = tmp[i];
            }
        }
        #pragma unroll
        for (int i = 0; i < 16; i++)
            sU[j*16 + i] = make_float2(st[i].re, st[i].im);
    }
    __syncthreads();

    // ---- per-lane constants ----
    float Ur[16], Ui[16];
    #pragma unroll
    for (int j = 0; j < 16; j++) {
        float2 u = sU[j*16 + p];
        Ur[j] = u.x; Ui[j] = u.y;
    }
    const float4 wrow = reinterpret_cast<const float4*>(W)[p];
    const float4 bv   = *reinterpret_cast<const float4*>(b);

    // conflict-free pooling column order: h=1 starts at column 3 (odd lane-
    // offset delta vs h=0 -> even/odd bank split, 32 lanes / 32 banks)
    int colOff[6];
    #pragma unroll
    for (int i = 0; i < 6; i++) {
        int c = i + 3*h; if (c >= 6) c -= 6;
        colOff[i] = c;
    }

    float runS0=0, runS1=0, runS2=0, runS3=0;
    float runQ0=0, runQ1=0, runQ2=0, runQ3=0;

    const int cb = p & 3, rb = p >> 2;
    const int poolOff = h*672 + rb*168 + cb*6;

    for (int t = 0; t < PAIRS; t++) {
        if (t + 1 < PAIRS) {
            issue(t + 1, (t + 1) & 1);
            asm volatile("cp.async.wait_group 1;\n");
        } else {
            asm volatile("cp.async.wait_group 0;\n");
        }
        __syncwarp();

        // ---- pooling for bin p of sample h ----
        const float* s0f = reinterpret_cast<const float*>(&smv[t & 1][w][0]) + poolOff;
        float v = 0.f;
        #pragma unroll
        for (int i = 0; i < 6; i++) {
            const float* cp_ = s0f + colOff[i];
            #pragma unroll
            for (int dr = 0; dr < 6; dr++)
                v += cp_[dr*28];
        }
        v *= (1.0f / 36.0f);

        // ---- feats = pooled @ W + b (butterfly within 16-lane half) ----
        float f0 = v*wrow.x, f1 = v*wrow.y, f2 = v*wrow.z, f3 = v*wrow.w;
        #pragma unroll
        for (int m = 1; m < 16; m <<= 1) {
            f0 += __shfl_xor_sync(0xffffffffu, f0, m);
            f1 += __shfl_xor_sync(0xffffffffu, f1, m);
            f2 += __shfl_xor_sync(0xffffffffu, f2, m);
            f3 += __shfl_xor_sync(0xffffffffu, f3, m);
        }
        f0 += bv.x; f1 += bv.y; f2 += bv.z; f3 += bv.w;

        // ---- encoded product-state magnitudes ----
        float c0_,s_0,c1_,s_1,c2_,s_2,c3_,s_3;
        __sincosf(0.5f*f0, &s_0, &c0_);
        __sincosf(0.5f*f1, &s_1, &c1_);
        __sincosf(0.5f*f2, &s_2, &c2_);
        __sincosf(0.5f*f3, &s_3, &c3_);
        float w01[4] = { c0_*c1_, c0_*s_1, s_0*c1_, s_0*s_1 };
        float w23[4] = { c2_*c3_, c2_*s_3, s_2*c3_, s_2*s_3 };

        // ---- amp_p = sum_j U[p][j] * m_j * (-i)^popc(j) ----
        float ar = 0.f, ai = 0.f;
        #pragma unroll
        for (int j = 0; j < 16; j++) {
            float m = w01[j >> 2] * w23[j & 3];
            const int pm = __popc(j) & 3;
            if      (pm == 0) { ar += Ur[j]*m; ai += Ui[j]*m; }
            else if (pm == 1) { ar += Ui[j]*m; ai -= Ur[j]*m; }
            else if (pm == 2) { ar -= Ur[j]*m; ai -= Ui[j]*m; }
            else              { ar -= Ui[j]*m; ai += Ur[j]*m; }
        }
        float prob = ar*ar + ai*ai;

        // ---- expZ: Walsh-Hadamard butterfly over 16-lane half ----
        float v4 = prob;
        #pragma unroll
        for (int m = 1; m < 16; m <<= 1) {
            float o = __shfl_xor_sync(0xffffffffu, v4, m);
            v4 = (p & m) ? (o - v4) : (v4 + o);
        }
        const int hb = h << 4;
        float z0 = __shfl_sync(0xffffffffu, v4, hb + 8);
        float z1 = __shfl_sync(0xffffffffu, v4, hb + 4);
        float z2 = __shfl_sync(0xffffffffu, v4, hb + 2);
        float z3 = __shfl_sync(0xffffffffu, v4, hb + 1);

        if (p == 0) {
            long s = samp(t) + h;
            reinterpret_cast<float4*>(out)[s] = make_float4(z0, z1, z2, z3);
            runS0 += z0; runS1 += z1; runS2 += z2; runS3 += z3;
            runQ0 += z0*z0; runQ1 += z1*z1; runQ2 += z2*z2; runQ3 += z3*z3;
        }
    }

    // combine halves (lanes 0 and 16 hold stats)
    runS0 += __shfl_xor_sync(0xffffffffu, runS0, 16);
    runS1 += __shfl_xor_sync(0xffffffffu, runS1, 16);
    runS2 += __shfl_xor_sync(0xffffffffu, runS2, 16);
    runS3 += __shfl_xor_sync(0xffffffffu, runS3, 16);
    runQ0 += __shfl_xor_sync(0xffffffffu, runQ0, 16);
    runQ1 += __shfl_xor_sync(0xffffffffu, runQ1, 16);
    runQ2 += __shfl_xor_sync(0xffffffffu, runQ2, 16);
    runQ3 += __shfl_xor_sync(0xffffffffu, runQ3, 16);

    if (lane == 0) {
        sPart[w][0] = runS0; sPart[w][1] = runS1;
        sPart[w][2] = runS2; sPart[w][3] = runS3;
        sPart[w][4] = runQ0; sPart[w][5] = runQ1;
        sPart[w][6] = runQ2; sPart[w][7] = runQ3;
    }
    __syncthreads();

    // ---- publish block partial + take ticket ----
    __shared__ unsigned sTicket;
    if (tid < 8) {
        float t = sPart[0][tid] + sPart[1][tid] + sPart[2][tid] + sPart[3][tid];
        g_part[bid * 8 + tid] = t;
    }
    __threadfence();
    if (tid == 0) sTicket = atomicAdd(&g_cnt, 1u);
    __syncthreads();

    if ((sTicket % GRID) == GRID - 1) {
        // ---- designated (last) block: reduce partials, compute scale/shift
        __threadfence();
        float* sRed = reinterpret_cast<float*>(sU);   // reuse 512-float scratch
        {
            int ch = tid & 7, row = tid >> 3;          // 16 rows x 8 channels
            float s = 0.f;
            #pragma unroll 4
            for (int q = row; q < GRID; q += 16) s += __ldcg(&g_part[q*8 + ch]);
            sRed[row*8 + ch] = s;
        }
        __syncthreads();
        if (tid < 8) {
            float tt = 0.f;
            #pragma unroll
            for (int r = 0; r < 16; r++) tt += sRed[r*8 + tid];
            sRed[256 + tid] = tt;
        }
        __syncthreads();
        if (tid < 4) {
            float invB = 1.0f / (float)B;
            float mu  = sRed[256 + tid] * invB;
            float var = sRed[260 + tid] * invB - mu*mu;    // biased var
            float scw = gamma[tid] * rsqrtf(var + 1e-5f);
            g_scale[tid]     = scw;
            g_scale[4 + tid] = beta[tid] - mu * scw;
        }
        __threadfence();
        __syncthreads();
        if (tid == 0) atomicAdd(&g_flag, 1u);   // bump epoch
    }

    // ---- all blocks: wait for epoch bump ----
    if (tid == 0) {
        while (*(volatile unsigned*)&g_flag == epoch) __nanosleep(64);
    }
    __syncthreads();
    __threadfence();

    if (tid < 8) sScale[tid] = *(volatile float*)&g_scale[tid];
    __syncthreads();

    // ---- normalize own samples: chunks c0 and c1, 64 f4 each ----
    {
        float4 scv = *reinterpret_cast<const float4*>(&sScale[0]);
        float4 shv = *reinterpret_cast<const float4*>(&sScale[4]);
        long i = ((tid < 64) ? c0 : c1) * SPCH + (tid & 63);
        float4 r = reinterpret_cast<float4*>(out)[i];
        r.x = r.x*scv.x + shv.x;
        r.y = r.y*scv.y + shv.y;
        r.z = r.z*scv.z + shv.z;
        r.w = r.w*scv.w + shv.w;
        reinterpret_cast<float4*>(out)[i] = r;
    }
}

// ---------------- launch ----------------------------------------------------
extern "C" void kernel_launch(void* const* d_in, const int* in_sizes, int n_in,
                              void* d_out, int out_size)
{
    const float* x     = (const float*)d_in[0];  // [B,1,28,28]
    const float* W     = (const float*)d_in[1];  // [16,4]
    const float* b     = (const float*)d_in[2];  // [4]
    const float* vp    = (const float*)d_in[3];  // [3,4,3]
    const float* gamma = (const float*)d_in[4];  // [4]
    const float* beta  = (const float*)d_in[5];  // [4]
    float* out = (float*)d_out;                  // [B,4]

    int B = in_sizes[0] / 784;                   // 65536

    k_all<<<GRID, 128>>>(x, W, b, vp, gamma, beta, out, B);
}